// round 2
// baseline (speedup 1.0000x reference)
#include <cuda_runtime.h>
#include <cstdint>

// Problem constants
#define BQ 16
#define NQ 4096
#define DQ 256
#define KQ 4096
#define MQ (BQ*NQ)   // 65536 tokens

#define DECAYF 0.99f
#define ONEMDECAYF 0.01f
#define EPSF 1e-5f

// ---------------- scratch (no allocations allowed) ----------------
__device__ unsigned long long g_best[MQ];   // (ordered-float score << 32) | index
__device__ float  g_enorm[KQ];
__device__ float  g_cs[KQ];
__device__ float  g_es[KQ*DQ];
__device__ double g_loss;
__device__ float  g_tot;

// ---------------- helpers ----------------
__device__ __forceinline__ unsigned long long fma2(unsigned long long a,
                                                   unsigned long long b,
                                                   unsigned long long c) {
    unsigned long long d;
    asm("fma.rn.f32x2 %0, %1, %2, %3;" : "=l"(d) : "l"(a), "l"(b), "l"(c));
    return d;
}
__device__ __forceinline__ unsigned long long bcast2(float x) {
    unsigned long long d;
    asm("mov.b64 %0, {%1, %1};" : "=l"(d) : "f"(x));
    return d;
}
__device__ __forceinline__ float2 unpack2(unsigned long long v) {
    float2 r;
    asm("mov.b64 {%0, %1}, %2;" : "=f"(r.x), "=f"(r.y) : "l"(v));
    return r;
}
// order-preserving float -> uint32 map (total order, matches fp32 compare)
__device__ __forceinline__ unsigned int fkey(float f) {
    unsigned int b = __float_as_uint(f);
    return b ^ ((b & 0x80000000u) ? 0xFFFFFFFFu : 0x80000000u);
}

// ---------------- init ----------------
__global__ void init_kernel() {
    int i = blockIdx.x * blockDim.x + threadIdx.x;
    if (i < MQ)     g_best[i] = 0xFFFFFFFFFFFFFFFFull;
    if (i < KQ)     g_cs[i]   = 0.f;
    if (i < KQ*DQ)  g_es[i]   = 0.f;
    if (i == 0) { g_loss = 0.0; g_tot = 0.f; }
}

// ---------------- ||e_k||^2 ----------------
__global__ void enorm_kernel(const float* __restrict__ embed) {
    int k = blockIdx.x;
    int t = threadIdx.x;                 // 64 threads, each 4 floats
    const float4* row = reinterpret_cast<const float4*>(embed + (size_t)k * DQ);
    float4 v = row[t];
    float s = v.x*v.x + v.y*v.y + v.z*v.z + v.w*v.w;
    #pragma unroll
    for (int off = 16; off; off >>= 1) s += __shfl_down_sync(0xffffffffu, s, off);
    __shared__ float sh[2];
    if ((t & 31) == 0) sh[t >> 5] = s;
    __syncthreads();
    if (t == 0) g_enorm[k] = sh[0] + sh[1];
}

// ---------------- fused distance GEMM + argmin ----------------
#define TBM 128
#define TBK 128
#define TD  16
#define SSTR 132   // padded row stride (floats), 16B aligned

__global__ __launch_bounds__(256, 2)
void dist_argmin_kernel(const float* __restrict__ z, const float* __restrict__ embed) {
    __shared__ __align__(16) float As[TD][SSTR];
    __shared__ __align__(16) float Bs[TD][SSTR];
    __shared__ float En[TBK];

    const int tid = threadIdx.x;
    const int tx = tid & 15;
    const int ty = tid >> 4;
    const int rowBase = blockIdx.y * TBM;
    const int colBase = blockIdx.x * TBK;

    if (tid < TBK) En[tid] = g_enorm[colBase + tid];

    unsigned long long acc[8][4];
    #pragma unroll
    for (int i = 0; i < 8; i++)
        #pragma unroll
        for (int p = 0; p < 4; p++) acc[i][p] = 0ull;   // (0.f, 0.f)

    for (int dBase = 0; dBase < DQ; dBase += TD) {
        #pragma unroll
        for (int l = 0; l < 2; l++) {
            int lin = tid + l * 256;            // 0..511
            int r   = lin >> 2;                 // 0..127
            int c4  = (lin & 3) << 2;           // 0,4,8,12
            float4 av = *reinterpret_cast<const float4*>(&z[(size_t)(rowBase + r) * DQ + dBase + c4]);
            As[c4+0][r] = av.x; As[c4+1][r] = av.y; As[c4+2][r] = av.z; As[c4+3][r] = av.w;
            float4 bv = *reinterpret_cast<const float4*>(&embed[(size_t)(colBase + r) * DQ + dBase + c4]);
            Bs[c4+0][r] = bv.x; Bs[c4+1][r] = bv.y; Bs[c4+2][r] = bv.z; Bs[c4+3][r] = bv.w;
        }
        __syncthreads();

        #pragma unroll
        for (int dd = 0; dd < TD; dd++) {
            float4 a0 = *reinterpret_cast<const float4*>(&As[dd][ty * 8]);
            float4 a1 = *reinterpret_cast<const float4*>(&As[dd][ty * 8 + 4]);
            ulonglong2 bq0 = *reinterpret_cast<const ulonglong2*>(&Bs[dd][tx * 8]);
            ulonglong2 bq1 = *reinterpret_cast<const ulonglong2*>(&Bs[dd][tx * 8 + 4]);
            float aN[8] = {a0.x, a0.y, a0.z, a0.w, a1.x, a1.y, a1.z, a1.w};
            #pragma unroll
            for (int i = 0; i < 8; i++) {
                unsigned long long ap = bcast2(aN[i]);
                acc[i][0] = fma2(ap, bq0.x, acc[i][0]);
                acc[i][1] = fma2(ap, bq0.y, acc[i][1]);
                acc[i][2] = fma2(ap, bq1.x, acc[i][2]);
                acc[i][3] = fma2(ap, bq1.y, acc[i][3]);
            }
        }
        __syncthreads();
    }

    // epilogue: per-row argmin over this block's 128 columns, then global atomicMin
    #pragma unroll
    for (int i = 0; i < 8; i++) {
        int row = rowBase + ty * 8 + i;
        unsigned long long bestKey = 0xFFFFFFFFFFFFFFFFull;
        #pragma unroll
        for (int p = 0; p < 4; p++) {
            float2 v = unpack2(acc[i][p]);
            int c0 = tx * 8 + 2 * p;
            float s0 = En[c0]     - 2.0f * v.x;
            float s1 = En[c0 + 1] - 2.0f * v.y;
            unsigned long long k0 = ((unsigned long long)fkey(s0) << 32) | (unsigned)(colBase + c0);
            unsigned long long k1 = ((unsigned long long)fkey(s1) << 32) | (unsigned)(colBase + c0 + 1);
            bestKey = min(bestKey, min(k0, k1));
        }
        #pragma unroll
        for (int off = 8; off; off >>= 1) {
            unsigned long long o = __shfl_down_sync(0xffffffffu, bestKey, off);
            bestKey = min(bestKey, o);
        }
        if (tx == 0) atomicMin(&g_best[row], bestKey);
    }
}

// ---------------- gather z_q, loss, segment sums ----------------
__global__ void gather_kernel(const float* __restrict__ z, const float* __restrict__ embed,
                              float* __restrict__ out_zq, float* __restrict__ out_idx) {
    int t = blockIdx.x;
    int d = threadIdx.x;  // 256
    unsigned long long best = g_best[t];
    int idx = (int)(unsigned)(best & 0xFFFFFFFFull);
    float zq = embed[(size_t)idx * DQ + d];
    float zv = z[(size_t)t * DQ + d];
    out_zq[(size_t)t * DQ + d] = zq;
    atomicAdd(&g_es[(size_t)idx * DQ + d], zv);
    float diff = zq - zv;
    float s = diff * diff;
    #pragma unroll
    for (int off = 16; off; off >>= 1) s += __shfl_down_sync(0xffffffffu, s, off);
    __shared__ float sh[8];
    if ((d & 31) == 0) sh[d >> 5] = s;
    __syncthreads();
    if (d == 0) {
        float tot = 0.f;
        #pragma unroll
        for (int w = 0; w < 8; w++) tot += sh[w];
        atomicAdd(&g_loss, (double)tot);
        out_idx[t] = (float)idx;
        atomicAdd(&g_cs[idx], 1.0f);
    }
}

// ---------------- EMA cluster size + total + loss write ----------------
__global__ void ncs_kernel(const float* __restrict__ cluster_size,
                           float* __restrict__ out_ncs, float* __restrict__ out_loss) {
    int k = blockIdx.x * blockDim.x + threadIdx.x;   // 4096
    float ncs = cluster_size[k] * DECAYF + ONEMDECAYF * g_cs[k];
    out_ncs[k] = ncs;
    float s = ncs;
    #pragma unroll
    for (int off = 16; off; off >>= 1) s += __shfl_down_sync(0xffffffffu, s, off);
    __shared__ float sh[8];
    int lt = threadIdx.x;
    if ((lt & 31) == 0) sh[lt >> 5] = s;
    __syncthreads();
    if (lt == 0) {
        float tot = 0.f;
        #pragma unroll
        for (int w = 0; w < 8; w++) tot += sh[w];
        atomicAdd(&g_tot, tot);
    }
    if (k == 0) out_loss[0] = (float)(2.0 * g_loss / (double)((size_t)MQ * DQ));
}

// ---------------- EMA embed_avg + normalized embed ----------------
__global__ void final_kernel(const float* __restrict__ embed_avg,
                             const float* __restrict__ out_ncs,
                             float* __restrict__ out_new_embed,
                             float* __restrict__ out_nea) {
    int i = blockIdx.x * blockDim.x + threadIdx.x;   // K*D
    int k = i >> 8;
    float tot = g_tot;
    float ncs = out_ncs[k];
    float csn = (ncs + EPSF) / (tot + (float)KQ * EPSF) * tot;
    float nea = embed_avg[i] * DECAYF + ONEMDECAYF * g_es[i];
    out_nea[i] = nea;
    out_new_embed[i] = nea / csn;
}

// ---------------- launch ----------------
extern "C" void kernel_launch(void* const* d_in, const int* in_sizes, int n_in,
                              void* d_out, int out_size) {
    const float* z            = (const float*)d_in[0];
    const float* embed        = (const float*)d_in[1];
    const float* cluster_size = (const float*)d_in[2];
    const float* embed_avg    = (const float*)d_in[3];

    float* out          = (float*)d_out;
    float* out_zq       = out;                                   // [B,N,D]
    float* out_idx      = out + (size_t)MQ * DQ;                 // [B,N]
    float* out_loss     = out_idx + MQ;                          // [1]
    float* out_newembed = out_loss + 1;                          // [K,D]
    float* out_ncs      = out_newembed + (size_t)KQ * DQ;        // [K]
    float* out_nea      = out_ncs + KQ;                          // [K,D]

    init_kernel<<<(KQ * DQ + 255) / 256, 256>>>();
    enorm_kernel<<<KQ, 64>>>(embed);
    dim3 grid(KQ / TBK, MQ / TBM);
    dist_argmin_kernel<<<grid, 256>>>(z, embed);
    gather_kernel<<<MQ, DQ>>>(z, embed, out_zq, out_idx);
    ncs_kernel<<<KQ / 256, 256>>>(cluster_size, out_ncs, out_loss);
    final_kernel<<<(KQ * DQ) / 256, 256>>>(embed_avg, out_ncs, out_newembed, out_nea);
}

// round 4
// speedup vs baseline: 1.7385x; 1.7385x over previous
#include <cuda_runtime.h>
#include <cuda_fp16.h>
#include <cstdint>

// Problem constants
#define BQ 16
#define NQ 4096
#define DQ 256
#define KQ 4096
#define MQ (BQ*NQ)   // 65536 tokens

#define DECAYF 0.99f
#define ONEMDECAYF 0.01f
#define EPSF 1e-5f

// GEMM config: fp16 2-way split, 3 segments -> K_eff = 768
#define KSEG 768
#define ROWB (KSEG*2)        // 1536 bytes per row of A_big/B_big
#define KC 32                // fp16 per k-chunk
#define NCHUNK (KSEG/KC)     // 24
#define STG 3
#define LDA 80               // smem row stride (bytes), conflict-free for ldmatrix
#define ATILE (128*LDA)      // 10240
#define STAGEB (2*ATILE)     // 20480 (A tile + B tile)
#define SMEM_DIST (STG*STAGEB + 512 + 1024)   // stages + En + sbest = 62976

// ---------------- device scratch (no allocations allowed) ----------------
__device__ __align__(16) __half g_zbig[(size_t)MQ * KSEG];   // [M][h0|h0|h1] (z*16)
__device__ __align__(16) __half g_ebig[(size_t)KQ * KSEG];   // [K][g0|g1|g0] (e*16)
__device__ unsigned long long g_best[MQ];   // (ordered score <<32)|index
__device__ float  g_enorm[KQ];
__device__ float  g_cs[KQ];
__device__ float  g_es[KQ*DQ];
__device__ double g_loss;
__device__ float  g_tot;

// ---------------- helpers ----------------
__device__ __forceinline__ uint32_t s2u(const void* p) {
    uint32_t a;
    asm("{ .reg .u64 t; cvta.to.shared.u64 t, %1; cvt.u32.u64 %0, t; }"
        : "=r"(a) : "l"(p));
    return a;
}
__device__ __forceinline__ unsigned int fkey(float f) {
    unsigned int b = __float_as_uint(f);
    return b ^ ((b & 0x80000000u) ? 0xFFFFFFFFu : 0x80000000u);
}
__device__ __forceinline__ unsigned long long umin64(unsigned long long a,
                                                     unsigned long long b) {
    return a < b ? a : b;
}
__device__ __forceinline__ void cp16(uint32_t dst, const void* src) {
    asm volatile("cp.async.cg.shared.global [%0], [%1], 16;" :: "r"(dst), "l"(src));
}
#define CP_COMMIT() asm volatile("cp.async.commit_group;" ::: "memory")

__device__ __forceinline__ void ldsm4(uint32_t& r0, uint32_t& r1, uint32_t& r2,
                                      uint32_t& r3, uint32_t a) {
    asm volatile("ldmatrix.sync.aligned.m8n8.x4.shared.b16 {%0,%1,%2,%3}, [%4];"
                 : "=r"(r0), "=r"(r1), "=r"(r2), "=r"(r3) : "r"(a));
}
__device__ __forceinline__ void mma16816(float* c, const uint32_t* a,
                                         uint32_t b0, uint32_t b1) {
    asm volatile(
        "mma.sync.aligned.m16n8k16.row.col.f32.f16.f16.f32 "
        "{%0,%1,%2,%3}, {%4,%5,%6,%7}, {%8,%9}, {%0,%1,%2,%3};"
        : "+f"(c[0]), "+f"(c[1]), "+f"(c[2]), "+f"(c[3])
        : "r"(a[0]), "r"(a[1]), "r"(a[2]), "r"(a[3]), "r"(b0), "r"(b1));
}

// ---------------- init ----------------
__global__ void init_kernel() {
    int i = blockIdx.x * blockDim.x + threadIdx.x;
    if (i < KQ)    g_cs[i] = 0.f;
    if (i < KQ*DQ) g_es[i] = 0.f;
    if (i == 0) { g_loss = 0.0; g_tot = 0.f; }
}

// ---------------- splits (scale x16, fp16 2-way Dekker) ----------------
__global__ void split_z_kernel(const float* __restrict__ z) {
    int i = blockIdx.x * blockDim.x + threadIdx.x;   // over M*D/2
    if (i >= MQ * DQ / 2) return;
    int idx = i * 2;
    int row = idx >> 8;
    int d = idx & 255;
    float2 v = *reinterpret_cast<const float2*>(z + idx);
    float sx = v.x * 16.0f, sy = v.y * 16.0f;
    __half hx0 = __float2half(sx), hy0 = __float2half(sy);
    __half hx1 = __float2half(sx - __half2float(hx0));
    __half hy1 = __float2half(sy - __half2float(hy0));
    __half* base = g_zbig + (size_t)row * KSEG + d;
    __half2 p0; p0.x = hx0; p0.y = hy0;
    __half2 p1; p1.x = hx1; p1.y = hy1;
    *reinterpret_cast<__half2*>(base)       = p0;   // seg0: h0
    *reinterpret_cast<__half2*>(base + 256) = p0;   // seg1: h0
    *reinterpret_cast<__half2*>(base + 512) = p1;   // seg2: h1
}
__global__ void split_e_kernel(const float* __restrict__ e) {
    int i = blockIdx.x * blockDim.x + threadIdx.x;   // over K*D/2
    if (i >= KQ * DQ / 2) return;
    int idx = i * 2;
    int row = idx >> 8;
    int d = idx & 255;
    float2 v = *reinterpret_cast<const float2*>(e + idx);
    float sx = v.x * 16.0f, sy = v.y * 16.0f;
    __half gx0 = __float2half(sx), gy0 = __float2half(sy);
    __half gx1 = __float2half(sx - __half2float(gx0));
    __half gy1 = __float2half(sy - __half2float(gy0));
    __half* base = g_ebig + (size_t)row * KSEG + d;
    __half2 p0; p0.x = gx0; p0.y = gy0;
    __half2 p1; p1.x = gx1; p1.y = gy1;
    *reinterpret_cast<__half2*>(base)       = p0;   // seg0: g0
    *reinterpret_cast<__half2*>(base + 256) = p1;   // seg1: g1
    *reinterpret_cast<__half2*>(base + 512) = p0;   // seg2: g0
}

// ---------------- ||e_k||^2 (unscaled fp32) ----------------
__global__ void enorm_kernel(const float* __restrict__ embed) {
    int k = blockIdx.x;
    int t = threadIdx.x;                 // 64 threads x 4 floats
    const float4* row = reinterpret_cast<const float4*>(embed + (size_t)k * DQ);
    float4 v = row[t];
    float s = v.x*v.x + v.y*v.y + v.z*v.z + v.w*v.w;
    #pragma unroll
    for (int off = 16; off; off >>= 1) s += __shfl_down_sync(0xffffffffu, s, off);
    __shared__ float sh[2];
    if ((t & 31) == 0) sh[t >> 5] = s;
    __syncthreads();
    if (t == 0) g_enorm[k] = sh[0] + sh[1];
}

// ---------------- stage loader ----------------
__device__ __forceinline__ void issue_stage(uint32_t smem_base, int buf,
                                            int mBase, int nBase, int kc) {
    const char* zB = (const char*)g_zbig;
    const char* eB = (const char*)g_ebig;
    uint32_t abase = smem_base + buf * STAGEB;
    uint32_t bbase = abase + ATILE;
    int kb = kc * (KC * 2);   // byte offset in row
    #pragma unroll
    for (int j = 0; j < 2; j++) {
        int id = threadIdx.x + j * 256;   // 0..511
        int r = id >> 2;
        int c = (id & 3) * 16;
        cp16(abase + r * LDA + c, zB + (size_t)(mBase + r) * ROWB + kb + c);
        cp16(bbase + r * LDA + c, eB + (size_t)(nBase + r) * ROWB + kb + c);
    }
}

// ---------------- fused HMMA distance GEMM + argmin ----------------
__global__ __launch_bounds__(256, 2)
void dist_hmma_kernel() {
    extern __shared__ char smem[];
    uint32_t smem_base = s2u(smem);
    const int tid = threadIdx.x;
    const int lane = tid & 31;
    const int wid = tid >> 5;
    const int wm = wid & 3;          // warp row group (4)
    const int wn = wid >> 2;         // warp col group (2)
    const int mBase = blockIdx.x * 128;

    float* En = (float*)(smem + STG * STAGEB);
    unsigned long long* sbest = (unsigned long long*)(smem + STG * STAGEB + 512);

    // per-lane ldmatrix offsets (bytes)
    const uint32_t aLane = (uint32_t)((wm * 32 + (lane & 15)) * LDA + ((lane & 16) ? 16 : 0));
    const uint32_t bLane = (uint32_t)((wn * 64 + ((lane >> 4) & 1) * 8 + (lane & 7)) * LDA
                                      + ((lane & 8) ? 16 : 0));

    unsigned long long best4[4];
    #pragma unroll
    for (int s = 0; s < 4; s++) best4[s] = 0xFFFFFFFFFFFFFFFFull;

    for (int nt = 0; nt < KQ / 128; nt++) {
        const int nBase = nt * 128;

        float c[2][8][4];
        #pragma unroll
        for (int mf = 0; mf < 2; mf++)
            #pragma unroll
            for (int nf = 0; nf < 8; nf++)
                #pragma unroll
                for (int r = 0; r < 4; r++) c[mf][nf][r] = 0.f;

        // prologue
        issue_stage(smem_base, 0, mBase, nBase, 0); CP_COMMIT();
        issue_stage(smem_base, 1, mBase, nBase, 1); CP_COMMIT();

        for (int kc = 0; kc < NCHUNK; kc++) {
            if (kc < NCHUNK - 2) {
                issue_stage(smem_base, (kc + 2) % STG, mBase, nBase, kc + 2);
                CP_COMMIT();
                asm volatile("cp.async.wait_group 2;" ::: "memory");
            } else if (kc == NCHUNK - 2) {
                asm volatile("cp.async.wait_group 1;" ::: "memory");
            } else {
                asm volatile("cp.async.wait_group 0;" ::: "memory");
            }
            __syncthreads();

            const uint32_t abase = smem_base + (kc % STG) * STAGEB;
            const uint32_t bbase = abase + ATILE;
            #pragma unroll
            for (int k16 = 0; k16 < 2; k16++) {
                const uint32_t kb = k16 * 32;
                uint32_t a[2][4];
                #pragma unroll
                for (int mf = 0; mf < 2; mf++)
                    ldsm4(a[mf][0], a[mf][1], a[mf][2], a[mf][3],
                          abase + aLane + mf * (16 * LDA) + kb);
                #pragma unroll
                for (int nfp = 0; nfp < 4; nfp++) {
                    uint32_t b0, b1, b2, b3;
                    ldsm4(b0, b1, b2, b3, bbase + bLane + nfp * (16 * LDA) + kb);
                    mma16816(c[0][2*nfp],   a[0], b0, b1);
                    mma16816(c[0][2*nfp+1], a[0], b2, b3);
                    mma16816(c[1][2*nfp],   a[1], b0, b1);
                    mma16816(c[1][2*nfp+1], a[1], b2, b3);
                }
            }
            __syncthreads();
        }

        // epilogue: scores + running argmin
        if (tid < 128) En[tid] = g_enorm[nBase + tid];
        __syncthreads();
        #pragma unroll
        for (int mf = 0; mf < 2; mf++)
            #pragma unroll
            for (int nf = 0; nf < 8; nf++)
                #pragma unroll
                for (int r = 0; r < 4; r++) {
                    int col = wn * 64 + nf * 8 + (lane & 3) * 2 + (r & 1);
                    float score = En[col] - 0.0078125f * c[mf][nf][r];   // 2/256 exact
                    unsigned long long key =
                        ((unsigned long long)fkey(score) << 32) | (unsigned)(nBase + col);
                    int slot = mf * 2 + (r >> 1);
                    best4[slot] = umin64(best4[slot], key);
                }
        __syncthreads();   // En reuse next nt
    }

    // quad reduction (lanes sharing a row differ only in lane&3)
    #pragma unroll
    for (int s = 0; s < 4; s++) {
        best4[s] = umin64(best4[s], __shfl_xor_sync(0xffffffffu, best4[s], 1));
        best4[s] = umin64(best4[s], __shfl_xor_sync(0xffffffffu, best4[s], 2));
    }
    if ((lane & 3) == 0 && wn == 0) {
        #pragma unroll
        for (int s = 0; s < 4; s++) {
            int row = wm * 32 + (s >> 1) * 16 + (s & 1) * 8 + (lane >> 2);
            sbest[row] = best4[s];
        }
    }
    __syncthreads();
    if ((lane & 3) == 0 && wn == 1) {
        #pragma unroll
        for (int s = 0; s < 4; s++) {
            int row = wm * 32 + (s >> 1) * 16 + (s & 1) * 8 + (lane >> 2);
            g_best[mBase + row] = umin64(sbest[row], best4[s]);
        }
    }
}

// ---------------- gather z_q, loss, segment sums ----------------
__global__ void gather_kernel(const float* __restrict__ z, const float* __restrict__ embed,
                              float* __restrict__ out_zq, float* __restrict__ out_idx) {
    int t = blockIdx.x;
    int d = threadIdx.x;  // 256
    unsigned long long best = g_best[t];
    int idx = (int)(unsigned)(best & 0xFFFFFFFFull);
    float zq = embed[(size_t)idx * DQ + d];
    float zv = z[(size_t)t * DQ + d];
    out_zq[(size_t)t * DQ + d] = zq;
    atomicAdd(&g_es[(size_t)idx * DQ + d], zv);
    float diff = zq - zv;
    float s = diff * diff;
    #pragma unroll
    for (int off = 16; off; off >>= 1) s += __shfl_down_sync(0xffffffffu, s, off);
    __shared__ float sh[8];
    if ((d & 31) == 0) sh[d >> 5] = s;
    __syncthreads();
    if (d == 0) {
        float tot = 0.f;
        #pragma unroll
        for (int w = 0; w < 8; w++) tot += sh[w];
        atomicAdd(&g_loss, (double)tot);
        out_idx[t] = (float)idx;
        atomicAdd(&g_cs[idx], 1.0f);
    }
}

// ---------------- EMA cluster size + total + loss write ----------------
__global__ void ncs_kernel(const float* __restrict__ cluster_size,
                           float* __restrict__ out_ncs, float* __restrict__ out_loss) {
    int k = blockIdx.x * blockDim.x + threadIdx.x;   // 4096
    float ncs = cluster_size[k] * DECAYF + ONEMDECAYF * g_cs[k];
    out_ncs[k] = ncs;
    float s = ncs;
    #pragma unroll
    for (int off = 16; off; off >>= 1) s += __shfl_down_sync(0xffffffffu, s, off);
    __shared__ float sh[8];
    int lt = threadIdx.x;
    if ((lt & 31) == 0) sh[lt >> 5] = s;
    __syncthreads();
    if (lt == 0) {
        float tot = 0.f;
        #pragma unroll
        for (int w = 0; w < 8; w++) tot += sh[w];
        atomicAdd(&g_tot, tot);
    }
    if (k == 0) out_loss[0] = (float)(2.0 * g_loss / (double)((size_t)MQ * DQ));
}

// ---------------- EMA embed_avg + normalized embed ----------------
__global__ void final_kernel(const float* __restrict__ embed_avg,
                             const float* __restrict__ out_ncs,
                             float* __restrict__ out_new_embed,
                             float* __restrict__ out_nea) {
    int i = blockIdx.x * blockDim.x + threadIdx.x;   // K*D
    int k = i >> 8;
    float tot = g_tot;
    float ncs = out_ncs[k];
    float csn = (ncs + EPSF) / (tot + (float)KQ * EPSF) * tot;
    float nea = embed_avg[i] * DECAYF + ONEMDECAYF * g_es[i];
    out_nea[i] = nea;
    out_new_embed[i] = nea / csn;
}

// ---------------- launch ----------------
extern "C" void kernel_launch(void* const* d_in, const int* in_sizes, int n_in,
                              void* d_out, int out_size) {
    const float* z            = (const float*)d_in[0];
    const float* embed        = (const float*)d_in[1];
    const float* cluster_size = (const float*)d_in[2];
    const float* embed_avg    = (const float*)d_in[3];

    float* out          = (float*)d_out;
    float* out_zq       = out;                                   // [B,N,D]
    float* out_idx      = out + (size_t)MQ * DQ;                 // [B,N]
    float* out_loss     = out_idx + MQ;                          // [1]
    float* out_newembed = out_loss + 1;                          // [K,D]
    float* out_ncs      = out_newembed + (size_t)KQ * DQ;        // [K]
    float* out_nea      = out_ncs + KQ;                          // [K,D]

    cudaFuncSetAttribute(dist_hmma_kernel,
                         cudaFuncAttributeMaxDynamicSharedMemorySize, SMEM_DIST);

    init_kernel<<<(KQ * DQ + 255) / 256, 256>>>();
    split_z_kernel<<<(MQ * DQ / 2 + 255) / 256, 256>>>(z);
    split_e_kernel<<<(KQ * DQ / 2 + 255) / 256, 256>>>(embed);
    enorm_kernel<<<KQ, 64>>>(embed);
    dist_hmma_kernel<<<MQ / 128, 256, SMEM_DIST>>>();
    gather_kernel<<<MQ, DQ>>>(z, embed, out_zq, out_idx);
    ncs_kernel<<<KQ / 256, 256>>>(cluster_size, out_ncs, out_loss);
    final_kernel<<<(KQ * DQ) / 256, 256>>>(embed_avg, out_ncs, out_newembed, out_nea);
}